// round 16
// baseline (speedup 1.0000x reference)
#include <cuda_runtime.h>
#include <cstdint>

#define EMBED   1024
#define KDIM    64
#define HEADS   16
#define BATCH   4
#define SEQ     2048
#define TOKENS  (BATCH * SEQ)      /* 8192 */
#define QKVW    (3 * EMBED)        /* 3072 */
#define BH      (BATCH * HEADS)    /* 64   */

// Scratch (allocation-free rule: __device__ globals)
__device__ float g_qkv[(size_t)TOKENS * QKVW];     // q(hi,scaled) | k(hi) | (V region unused)
__device__ float g_qlo[(size_t)TOKENS * EMBED];    // Q lo-plane (scaled)
__device__ float g_klo[(size_t)TOKENS * EMBED];    // K lo-plane
__device__ float g_vt[(size_t)BH * KDIM * SEQ];    // V^T per (b,h): [d][tok], tf32-rounded
__device__ float g_heads[(size_t)TOKENS * EMBED];  // flash out, tf32-rounded
__device__ float g_wthi[(size_t)QKVW * EMBED];     // Wqkv^T: hi plane (V region: plain tf32r)
__device__ float g_wtlo[(size_t)2 * EMBED * EMBED];// Wq,Wk^T lo plane (raw - hi)
__device__ float g_wt2[(size_t)EMBED * EMBED];     // w^T, tf32-rounded

__device__ __forceinline__ float tf32r(float a) {   // round-to-nearest tf32
    uint32_t u;
    asm("cvt.rna.tf32.f32 %0, %1;" : "=r"(u) : "f"(a));
    return __uint_as_float(u);
}

__device__ __forceinline__ void mma8(float* c, const uint32_t* a, uint32_t b0, uint32_t b1) {
    asm volatile(
        "mma.sync.aligned.m16n8k8.row.col.f32.tf32.tf32.f32 "
        "{%0,%1,%2,%3}, {%4,%5,%6,%7}, {%8,%9}, {%0,%1,%2,%3};"
        : "+f"(c[0]), "+f"(c[1]), "+f"(c[2]), "+f"(c[3])
        : "r"(a[0]), "r"(a[1]), "r"(a[2]), "r"(a[3]), "r"(b0), "r"(b1));
}

__device__ __forceinline__ uint32_t s2u(const void* p) {
    return (uint32_t)__cvta_generic_to_shared(p);
}
__device__ __forceinline__ void cpa16(uint32_t dst, const void* src) {
    asm volatile("cp.async.ca.shared.global [%0], [%1], 16;" :: "r"(dst), "l"(src));
}

// ---------------------------------------------------------------------------
// Prep (tiled transpose + pre-split/pre-round):
//   j < 2048 (Q,K):  g_wthi = tf32r(W^T), g_wtlo = W^T - hi
//   j >= 2048 (V):   g_wthi = tf32r(W^T)
//   g_wt2 = tf32r(w^T)
// ---------------------------------------------------------------------------
__global__ void __launch_bounds__(256) prep_kernel(
    const float* __restrict__ wq, const float* __restrict__ wk,
    const float* __restrict__ wv, const float* __restrict__ w)
{
    __shared__ float tile[32][33];
    const int bid = blockIdx.x;
    const int tx = threadIdx.x & 31, ty = threadIdx.x >> 5;   // 32 x 8

    if (bid < 3072) {
        const int slice = bid >> 6;          // 0..47
        const int rem   = bid & 63;
        const int dt = rem >> 1, kt = rem & 1;
        const int which = slice >> 4, h = slice & 15;
        const float* wsel = (which == 0) ? wq : (which == 1) ? wk : wv;
        const float* src = wsel + (size_t)h * EMBED * KDIM;
        const int d0 = dt * 32, kc0 = kt * 32;
#pragma unroll
        for (int i = 0; i < 4; i++)
            tile[ty + i * 8][tx] = src[(size_t)(d0 + ty + i * 8) * KDIM + kc0 + tx];
        __syncthreads();
#pragma unroll
        for (int i = 0; i < 4; i++) {
            const int j = slice * 64 + kc0 + ty + i * 8;
            const float v = tile[tx][ty + i * 8];
            const float hh = tf32r(v);
            g_wthi[(size_t)j * EMBED + d0 + tx] = hh;
            if (which < 2)
                g_wtlo[(size_t)j * EMBED + d0 + tx] = v - hh;
        }
    } else {
        const int b2 = bid - 3072;           // 0..1023
        const int kt = b2 >> 5, jt = b2 & 31;
        const int k0 = kt * 32, j0 = jt * 32;
#pragma unroll
        for (int i = 0; i < 4; i++)
            tile[ty + i * 8][tx] = w[(size_t)(k0 + ty + i * 8) * EMBED + j0 + tx];
        __syncthreads();
#pragma unroll
        for (int i = 0; i < 4; i++)
            g_wt2[(size_t)(j0 + ty + i * 8) * EMBED + k0 + tx] = tf32r(tile[tx][ty + i * 8]);
    }
}

// ---------------------------------------------------------------------------
// Warp-mma tf32 GEMM:  C[128, 128] = A[128, 1024] @ B^T.
// cp.async double-buffered RAW staging.
//   SPLIT=3 (QKV3): A raw, split in regs (lo unrounded); B pre-split hi/lo
//                   planes from global (zero B-side ALU).
//   SPLIT=1, QKV  : A raw (cvt); B pre-rounded (no cvt).
//   OPROJ         : A pre-rounded (no cvt); B pre-rounded (no cvt).
// Epilogues: QKV3 -> Q scale+split / K split planes; QKV1 -> direct V^T
// (tf32r) into g_vt; OPROJ -> plain.
// ---------------------------------------------------------------------------
#define MODE_QKV   0
#define MODE_OPROJ 3

#define PA 36                 /* smem pitch (floats): conflict-free fragment LDS */
#define PEPI 132

template <int MODE, int SPLIT>
__global__ void __launch_bounds__(256, 2) gemm_kernel(
    const float* __restrict__ x, float* __restrict__ outp, int bx0)
{
    extern __shared__ float sf[];
    constexpr int NCH = 32;                     /* K = 1024, chunk 32 */
    constexpr int NPL = (SPLIT == 3) ? 3 : 2;   /* planes per stage   */
    constexpr int GSTG = NPL * 128 * PA;
    constexpr bool ACVT = (MODE == MODE_QKV);   /* OPROJ A pre-rounded */

    const int tid  = threadIdx.x;
    const int wid  = tid >> 5;
    const int lane = tid & 31;
    const int g    = lane >> 2;
    const int t    = lane & 3;
    const int wm   = (wid & 3) * 32;
    const int wn   = (wid >> 2) * 64;
    const int bm   = blockIdx.y * 128;

    const float* Abase; const float* Bhi; const float* Blo = nullptr;
    float* Cbase; int ldc;
    int j0 = 0;

    if constexpr (MODE == MODE_QKV) {
        j0 = (blockIdx.x + bx0) * 128;
        Abase = x + (size_t)bm * EMBED;
        Bhi   = g_wthi + (size_t)j0 * EMBED;
        if constexpr (SPLIT == 3) Blo = g_wtlo + (size_t)j0 * EMBED;
        Cbase = g_qkv + (size_t)bm * QKVW + j0;               ldc = QKVW;
    } else { /* OPROJ */
        Abase = g_heads + (size_t)bm * EMBED;
        Bhi   = g_wt2 + (size_t)blockIdx.x * 128 * EMBED;
        Cbase = outp + (size_t)bm * EMBED + blockIdx.x * 128; ldc = EMBED;
    }

    auto fill = [&](int ci, float* stg) {
        const int k0 = ci * 32;
#pragma unroll
        for (int p = 0; p < 4; ++p) {
            const int id = tid + p * 256;
            const int row = id >> 3, ch = (id & 7) * 4;
            cpa16(s2u(stg + row * PA + ch),            Abase + (size_t)row * EMBED + k0 + ch);
            cpa16(s2u(stg + 128 * PA + row * PA + ch), Bhi + (size_t)row * EMBED + k0 + ch);
            if constexpr (SPLIT == 3)
                cpa16(s2u(stg + 256 * PA + row * PA + ch), Blo + (size_t)row * EMBED + k0 + ch);
        }
        asm volatile("cp.async.commit_group;");
    };

    float acc[2][8][4];
#pragma unroll
    for (int mt = 0; mt < 2; mt++)
#pragma unroll
        for (int nt = 0; nt < 8; nt++)
#pragma unroll
            for (int i = 0; i < 4; i++) acc[mt][nt][i] = 0.f;

    fill(0, sf);   // prologue

    for (int ci = 0; ci < NCH; ++ci) {
        float* cur = sf + (ci & 1) * GSTG;
        if (ci + 1 < NCH) {
            fill(ci + 1, sf + ((ci + 1) & 1) * GSTG);
            asm volatile("cp.async.wait_group 1;");
        } else {
            asm volatile("cp.async.wait_group 0;");
        }
        __syncthreads();

        const float* aR   = cur;
        const float* bHiR = cur + 128 * PA;
        const float* bLoR = cur + 256 * PA;

#pragma unroll
        for (int ks = 0; ks < 4; ++ks) {
            const int kb = ks * 8;
            uint32_t aH[2][4], aL[2][4];
#pragma unroll
            for (int mt = 0; mt < 2; ++mt) {
                const float* ap = aR + (wm + mt * 16 + g) * PA + kb + t;
                const float r0 = ap[0], r1 = ap[8 * PA], r2 = ap[4], r3 = ap[8 * PA + 4];
                float h0, h1, h2, h3;
                if constexpr (ACVT) {
                    h0 = tf32r(r0); h1 = tf32r(r1); h2 = tf32r(r2); h3 = tf32r(r3);
                } else {
                    h0 = r0; h1 = r1; h2 = r2; h3 = r3;
                }
                aH[mt][0] = __float_as_uint(h0);
                aH[mt][1] = __float_as_uint(h1);
                aH[mt][2] = __float_as_uint(h2);
                aH[mt][3] = __float_as_uint(h3);
                if constexpr (SPLIT == 3) {
                    aL[mt][0] = __float_as_uint(r0 - h0);   // lo unrounded (mma truncates)
                    aL[mt][1] = __float_as_uint(r1 - h1);
                    aL[mt][2] = __float_as_uint(r2 - h2);
                    aL[mt][3] = __float_as_uint(r3 - h3);
                }
            }
#pragma unroll
            for (int nt = 0; nt < 8; ++nt) {
                const float* bh = bHiR + (wn + nt * 8 + g) * PA + kb + t;
                const uint32_t bH0 = __float_as_uint(bh[0]);
                const uint32_t bH1 = __float_as_uint(bh[4]);
#pragma unroll
                for (int mt = 0; mt < 2; ++mt) mma8(acc[mt][nt], aH[mt], bH0, bH1);
                if constexpr (SPLIT == 3) {
                    const float* bl = bLoR + (wn + nt * 8 + g) * PA + kb + t;
                    const uint32_t bL0 = __float_as_uint(bl[0]);
                    const uint32_t bL1 = __float_as_uint(bl[4]);
#pragma unroll
                    for (int mt = 0; mt < 2; ++mt) {
                        mma8(acc[mt][nt], aH[mt], bL0, bL1);
                        mma8(acc[mt][nt], aL[mt], bH0, bH1);
                    }
                }
            }
        }
        __syncthreads();   // all warps done with `cur` before it is refilled
    }

    // ---- epilogue: stage C through smem ----
#pragma unroll
    for (int mt = 0; mt < 2; ++mt)
#pragma unroll
        for (int nt = 0; nt < 8; ++nt) {
            const int row = wm + mt * 16 + g;
            const int col = wn + nt * 8 + t * 2;
            *(float2*)&sf[row * PEPI + col]       = make_float2(acc[mt][nt][0], acc[mt][nt][1]);
            *(float2*)&sf[(row + 8) * PEPI + col] = make_float2(acc[mt][nt][2], acc[mt][nt][3]);
        }
    __syncthreads();

    if constexpr (MODE == MODE_QKV && SPLIT == 1) {
        // V region: transposed tf32r write into g_vt[bh][d][tok].
        const int jv = j0 - 2 * EMBED;
        const int b  = bm >> 11;             // SEQ = 2048
        const int tl = bm & (SEQ - 1);
        const int r0 = tid & 7;
#pragma unroll
        for (int cc = 0; cc < 4; ++cc) {
            const int col = cc * 32 + (tid >> 3);
            const int hh  = (jv + col) >> 6;
            const int dd  = (jv + col) & (KDIM - 1);
            float* dst = g_vt + ((size_t)(b * HEADS + hh) * KDIM + dd) * SEQ + tl;
#pragma unroll
            for (int u = 0; u < 16; ++u) {
                const int r = r0 + u * 8;
                dst[r] = tf32r(sf[r * PEPI + col]);
            }
        }
    } else {
#pragma unroll
        for (int i = tid; i < 128 * 32; i += 256) {
            const int row = i >> 5, c4 = (i & 31) * 4;
            float4 v = *(const float4*)&sf[row * PEPI + c4];
            if constexpr (MODE == MODE_QKV && SPLIT == 3) {
                if (j0 < EMBED) {
                    // Q region: scale by 1/8, split hi/lo (lo unrounded)
                    v.x *= 0.125f; v.y *= 0.125f; v.z *= 0.125f; v.w *= 0.125f;
                    float4 hh, ll;
                    hh.x = tf32r(v.x); ll.x = v.x - hh.x;
                    hh.y = tf32r(v.y); ll.y = v.y - hh.y;
                    hh.z = tf32r(v.z); ll.z = v.z - hh.z;
                    hh.w = tf32r(v.w); ll.w = v.w - hh.w;
                    *(float4*)(Cbase + (size_t)row * ldc + c4) = hh;
                    *(float4*)(g_qlo + (size_t)(bm + row) * EMBED + j0 + c4) = ll;
                } else {
                    // K region: split hi/lo (lo unrounded)
                    float4 hh, ll;
                    hh.x = tf32r(v.x); ll.x = v.x - hh.x;
                    hh.y = tf32r(v.y); ll.y = v.y - hh.y;
                    hh.z = tf32r(v.z); ll.z = v.z - hh.z;
                    hh.w = tf32r(v.w); ll.w = v.w - hh.w;
                    *(float4*)(Cbase + (size_t)row * ldc + c4) = hh;
                    *(float4*)(g_klo + (size_t)(bm + row) * EMBED + (j0 - EMBED) + c4) = ll;
                }
            } else {
                *(float4*)(Cbase + (size_t)row * ldc + c4) = v;
            }
        }
    }
}

#define GEMM_SMEM3 ((2 * 3 * 128 * PA) * 4 > 128 * PEPI * 4 ? (2 * 3 * 128 * PA) * 4 : 128 * PEPI * 4)
#define GEMM_SMEM1 ((2 * 2 * 128 * PA) * 4 > 128 * PEPI * 4 ? (2 * 2 * 128 * PA) * 4 : 128 * PEPI * 4)

// ---------------------------------------------------------------------------
// Flash attention (R14-measured 887us, unchanged except tf32r on output):
// fused QK^T (3xTF32) + online softmax + PV (tf32). BM=128/CTA, 8 warps x
// 16 rows; 64-key tiles, double-buffered cp.async; Q pre-scaled/pre-split.
// ---------------------------------------------------------------------------
#define FPQ 68             /* pitch mod 32 = 4 -> ALL scalar patterns conflict-free */
#define STG_ROWS 192       /* Kh 64 + Kl 64 + Vt 64 */
#define FLASH_SMEM ((128 * 2 + 2 * STG_ROWS + 128) * FPQ * 4)  /* 208896 B */
#define NKT (SEQ / 64)     /* 32 key tiles */

__global__ void __launch_bounds__(256) flash_kernel()
{
    extern __shared__ float sf[];
    float* Qh  = sf;                       // [row][d]   128 x 64 (hi, scaled)
    float* Ql  = Qh + 128 * FPQ;
    float* St0 = Ql + 128 * FPQ;           // stage 0: Kh|Kl|Vt (64 rows each)
    float* St1 = St0 + STG_ROWS * FPQ;     // stage 1
    float* Ps  = St1 + STG_ROWS * FPQ;     // [row][tok] 128 x 64

    const int tid = threadIdx.x, wid = tid >> 5, lane = tid & 31;
    const int g = lane >> 2, t = lane & 3;
    const int wm = wid * 16;
    const int bm = blockIdx.x * 128;
    const int bh = blockIdx.y, b = bh >> 4, h = bh & (HEADS - 1);

    const float* qhi = g_qkv + (size_t)b * SEQ * QKVW + h * KDIM;
    const float* qlo = g_qlo + (size_t)b * SEQ * EMBED + h * KDIM;
    const float* khi = qhi + EMBED;
    const float* klo = g_klo + (size_t)b * SEQ * EMBED + h * KDIM;
    const float* vtg = g_vt + (size_t)bh * KDIM * SEQ;

    auto fill = [&](int kt0, float* stg) {
        float* Kh = stg;
        float* Kl = stg + 64 * FPQ;
        float* Vt = stg + 128 * FPQ;
#pragma unroll
        for (int p = 0; p < 4; ++p) {
            const int id = tid + p * 256;
            const int row = id >> 4, ch = (id & 15) * 4;
            cpa16(s2u(Kh + row * FPQ + ch), khi + (size_t)(kt0 + row) * QKVW + ch);
            cpa16(s2u(Kl + row * FPQ + ch), klo + (size_t)(kt0 + row) * EMBED + ch);
            cpa16(s2u(Vt + row * FPQ + ch), vtg + (size_t)row * SEQ + kt0 + ch);
        }
        asm volatile("cp.async.commit_group;");
    };

    // Q prologue: pure async copies (group A), then tile-0 fill (group B)
#pragma unroll
    for (int p = 0; p < 8; ++p) {
        const int id = tid + p * 256;
        const int row = id >> 4, ch = (id & 15) * 4;
        cpa16(s2u(Qh + row * FPQ + ch), qhi + (size_t)(bm + row) * QKVW + ch);
        cpa16(s2u(Ql + row * FPQ + ch), qlo + (size_t)(bm + row) * EMBED + ch);
    }
    asm volatile("cp.async.commit_group;");
    fill(0, St0);
    asm volatile("cp.async.wait_group 1;");   // Q copies complete
    __syncthreads();

    // Hoist Q fragments to registers (scalar LDS, conflict-free at pitch 68)
    uint32_t qh[8][4], ql[8][4];
#pragma unroll
    for (int ks = 0; ks < 8; ++ks) {
        const float* ap = Qh + (wm + g) * FPQ + ks * 8 + t;
        const float* al = Ql + (wm + g) * FPQ + ks * 8 + t;
        qh[ks][0] = __float_as_uint(ap[0]);
        qh[ks][1] = __float_as_uint(ap[8 * FPQ]);
        qh[ks][2] = __float_as_uint(ap[4]);
        qh[ks][3] = __float_as_uint(ap[8 * FPQ + 4]);
        ql[ks][0] = __float_as_uint(al[0]);
        ql[ks][1] = __float_as_uint(al[8 * FPQ]);
        ql[ks][2] = __float_as_uint(al[4]);
        ql[ks][3] = __float_as_uint(al[8 * FPQ + 4]);
    }

    float m0 = -1e30f, m1 = -1e30f, l0s = 0.f, l1s = 0.f;
    float o[8][4];
#pragma unroll
    for (int nt = 0; nt < 8; nt++)
#pragma unroll
        for (int i = 0; i < 4; i++) o[nt][i] = 0.f;

    for (int it = 0; it < NKT; ++it) {
        float* cur = (it & 1) ? St1 : St0;
        if (it + 1 < NKT) {
            fill((it + 1) * 64, (it & 1) ? St0 : St1);
            asm volatile("cp.async.wait_group 1;");
        } else {
            asm volatile("cp.async.wait_group 0;");
        }
        __syncthreads();

        float* Kh = cur;
        float* Kl = cur + 64 * FPQ;
        float* Vt = cur + 128 * FPQ;

        // S = Q K^T (3xTF32)
        float s[8][4];
#pragma unroll
        for (int nt = 0; nt < 8; nt++)
#pragma unroll
            for (int i = 0; i < 4; i++) s[nt][i] = 0.f;
#pragma unroll
        for (int ks = 0; ks < 8; ++ks) {
#pragma unroll
            for (int nt = 0; nt < 8; ++nt) {
                const float* bp = Kh + (nt * 8 + g) * FPQ + ks * 8 + t;
                const float* bl = Kl + (nt * 8 + g) * FPQ + ks * 8 + t;
                const uint32_t bH0 = __float_as_uint(bp[0]);
                const uint32_t bH1 = __float_as_uint(bp[4]);
                const uint32_t bL0 = __float_as_uint(bl[0]);
                const uint32_t bL1 = __float_as_uint(bl[4]);
                mma8(s[nt], qh[ks], bH0, bH1);
                mma8(s[nt], qh[ks], bL0, bL1);
                mma8(s[nt], ql[ks], bH0, bH1);
            }
        }

        // Online softmax (rows wm+g and wm+g+8; stats shared within quad)
        float mx0 = -1e30f, mx1 = -1e30f;
#pragma unroll
        for (int nt = 0; nt < 8; nt++) {
            mx0 = fmaxf(mx0, fmaxf(s[nt][0], s[nt][1]));
            mx1 = fmaxf(mx1, fmaxf(s[nt][2], s[nt][3]));
        }
        mx0 = fmaxf(mx0, __shfl_xor_sync(~0u, mx0, 1));
        mx0 = fmaxf(mx0, __shfl_xor_sync(~0u, mx0, 2));
        mx1 = fmaxf(mx1, __shfl_xor_sync(~0u, mx1, 1));
        mx1 = fmaxf(mx1, __shfl_xor_sync(~0u, mx1, 2));
        const float mn0 = fmaxf(m0, mx0), mn1 = fmaxf(m1, mx1);
        const float cr0 = __expf(m0 - mn0), cr1 = __expf(m1 - mn1);
        m0 = mn0; m1 = mn1;
        float ls0 = 0.f, ls1 = 0.f;
#pragma unroll
        for (int nt = 0; nt < 8; nt++) {
            s[nt][0] = __expf(s[nt][0] - mn0);
            s[nt][1] = __expf(s[nt][1] - mn0);
            s[nt][2] = __expf(s[nt][2] - mn1);
            s[nt][3] = __expf(s[nt][3] - mn1);
            ls0 += s[nt][0] + s[nt][1];
            ls1 += s[nt][2] + s[nt][3];
        }
        ls0 += __shfl_xor_sync(~0u, ls0, 1);
        ls0 += __shfl_xor_sync(~0u, ls0, 2);
        ls1 += __shfl_xor_sync(~0u, ls1, 1);
        ls1 += __shfl_xor_sync(~0u, ls1, 2);
        l0s = l0s * cr0 + ls0;
        l1s = l1s * cr1 + ls1;
#pragma unroll
        for (int nt = 0; nt < 8; nt++) {
            o[nt][0] *= cr0; o[nt][1] *= cr0;
            o[nt][2] *= cr1; o[nt][3] *= cr1;
        }

        // Stage P (C-frag layout -> A-frag layout), warp-private rows
#pragma unroll
        for (int nt = 0; nt < 8; nt++) {
            *(float2*)&Ps[(wm + g) * FPQ + nt * 8 + 2 * t] =
                make_float2(tf32r(s[nt][0]), tf32r(s[nt][1]));
            *(float2*)&Ps[(wm + g + 8) * FPQ + nt * 8 + 2 * t] =
                make_float2(tf32r(s[nt][2]), tf32r(s[nt][3]));
        }
        __syncwarp();

        // O += P V (1xTF32)
#pragma unroll
        for (int ks = 0; ks < 8; ++ks) {
            uint32_t a[4];
            const float* ap = Ps + (wm + g) * FPQ + ks * 8 + t;
            a[0] = __float_as_uint(ap[0]);
            a[1] = __float_as_uint(ap[8 * FPQ]);
            a[2] = __float_as_uint(ap[4]);
            a[3] = __float_as_uint(ap[8 * FPQ + 4]);
#pragma unroll
            for (int nt = 0; nt < 8; ++nt) {
                const float* bp = Vt + (nt * 8 + g) * FPQ + ks * 8 + t;
                mma8(o[nt], a, __float_as_uint(bp[0]), __float_as_uint(bp[4]));
            }
        }
        __syncthreads();
    }

    // Epilogue: normalize, pre-round for OPROJ, write heads
    const float i0 = 1.f / l0s, i1 = 1.f / l1s;
    float* dst0 = g_heads + (size_t)(b * SEQ + bm + wm + g) * EMBED + h * KDIM;
    float* dst1 = dst0 + 8 * EMBED;
#pragma unroll
    for (int nt = 0; nt < 8; nt++) {
        *(float2*)(dst0 + nt * 8 + 2 * t) =
            make_float2(tf32r(o[nt][0] * i0), tf32r(o[nt][1] * i0));
        *(float2*)(dst1 + nt * 8 + 2 * t) =
            make_float2(tf32r(o[nt][2] * i1), tf32r(o[nt][3] * i1));
    }
}

// ---------------------------------------------------------------------------
extern "C" void kernel_launch(void* const* d_in, const int* in_sizes, int n_in,
                              void* d_out, int out_size)
{
    const float* x  = (const float*)d_in[0];
    const float* wq = (const float*)d_in[1];
    const float* wk = (const float*)d_in[2];
    const float* wv = (const float*)d_in[3];
    const float* w  = (const float*)d_in[4];
    float* out = (float*)d_out;

    cudaFuncSetAttribute(gemm_kernel<MODE_QKV,   3>,
                         cudaFuncAttributeMaxDynamicSharedMemorySize, GEMM_SMEM3);
    cudaFuncSetAttribute(gemm_kernel<MODE_QKV,   1>,
                         cudaFuncAttributeMaxDynamicSharedMemorySize, GEMM_SMEM1);
    cudaFuncSetAttribute(gemm_kernel<MODE_OPROJ, 1>,
                         cudaFuncAttributeMaxDynamicSharedMemorySize, GEMM_SMEM1);
    cudaFuncSetAttribute(flash_kernel,
                         cudaFuncAttributeMaxDynamicSharedMemorySize, FLASH_SMEM);

    // 0. transpose + pre-split/pre-round weights once
    prep_kernel<<<4096, 256>>>(wq, wk, wv, w);

    // 1a. Q,K projection (3xTF32, B pre-split): cols [0,2048)
    gemm_kernel<MODE_QKV, 3>
        <<<dim3(16, TOKENS / 128), 256, GEMM_SMEM3>>>(x, out, 0);

    // 1b. V projection (1xTF32, B pre-rounded): cols [2048,3072);
    //     epilogue writes g_vt[bh][d][tok] directly (transposed, tf32r).
    gemm_kernel<MODE_QKV, 1>
        <<<dim3(8, TOKENS / 128), 256, GEMM_SMEM1>>>(x, out, 16);

    // 2. fused attention: g_heads = softmax(Q K^T / 8) V  (tf32r output)
    flash_kernel<<<dim3(SEQ / 128, BH), 256, FLASH_SMEM>>>();

    // 3. output projection (tf32, both operands pre-rounded): out = heads @ w
    gemm_kernel<MODE_OPROJ, 1>
        <<<dim3(EMBED / 128, TOKENS / 128), 256, GEMM_SMEM1>>>(x, out, 0);
}

// round 17
// speedup vs baseline: 1.0182x; 1.0182x over previous
#include <cuda_runtime.h>
#include <cstdint>

#define EMBED   1024
#define KDIM    64
#define HEADS   16
#define BATCH   4
#define SEQ     2048
#define TOKENS  (BATCH * SEQ)      /* 8192 */
#define QKVW    (3 * EMBED)        /* 3072 */
#define BH      (BATCH * HEADS)    /* 64   */

// Scratch (allocation-free rule: __device__ globals)
__device__ float g_qkv[(size_t)TOKENS * QKVW];     // q(hi,scaled) | k(hi) | (V region unused)
__device__ float g_qlo[(size_t)TOKENS * EMBED];    // Q lo-plane (scaled)
__device__ float g_klo[(size_t)TOKENS * EMBED];    // K lo-plane
__device__ float g_vt[(size_t)BH * KDIM * SEQ];    // V^T per (b,h): [d][tok], tf32-rounded
__device__ float g_heads[(size_t)TOKENS * EMBED];  // flash out, tf32-rounded
__device__ float g_wt[(size_t)QKVW * EMBED];       // Wqkv^T: Q,K raw; V region tf32-rounded
__device__ float g_wt2[(size_t)EMBED * EMBED];     // w^T, tf32-rounded

__device__ __forceinline__ float tf32r(float a) {   // round-to-nearest tf32
    uint32_t u;
    asm("cvt.rna.tf32.f32 %0, %1;" : "=r"(u) : "f"(a));
    return __uint_as_float(u);
}

__device__ __forceinline__ void mma8(float* c, const uint32_t* a, uint32_t b0, uint32_t b1) {
    asm volatile(
        "mma.sync.aligned.m16n8k8.row.col.f32.tf32.tf32.f32 "
        "{%0,%1,%2,%3}, {%4,%5,%6,%7}, {%8,%9}, {%0,%1,%2,%3};"
        : "+f"(c[0]), "+f"(c[1]), "+f"(c[2]), "+f"(c[3])
        : "r"(a[0]), "r"(a[1]), "r"(a[2]), "r"(a[3]), "r"(b0), "r"(b1));
}

__device__ __forceinline__ uint32_t s2u(const void* p) {
    return (uint32_t)__cvta_generic_to_shared(p);
}
__device__ __forceinline__ void cpa16(uint32_t dst, const void* src) {
    asm volatile("cp.async.ca.shared.global [%0], [%1], 16;" :: "r"(dst), "l"(src));
}

// ---------------------------------------------------------------------------
// Prep (tiled transpose): g_wt[j][d] = Wqkv^T (V region tf32-rounded);
// g_wt2[n][k] = tf32r(w^T).
// ---------------------------------------------------------------------------
__global__ void __launch_bounds__(256) prep_kernel(
    const float* __restrict__ wq, const float* __restrict__ wk,
    const float* __restrict__ wv, const float* __restrict__ w)
{
    __shared__ float tile[32][33];
    const int bid = blockIdx.x;
    const int tx = threadIdx.x & 31, ty = threadIdx.x >> 5;   // 32 x 8

    if (bid < 3072) {
        const int slice = bid >> 6;          // 0..47
        const int rem   = bid & 63;
        const int dt = rem >> 1, kt = rem & 1;
        const int which = slice >> 4, h = slice & 15;
        const float* wsel = (which == 0) ? wq : (which == 1) ? wk : wv;
        const float* src = wsel + (size_t)h * EMBED * KDIM;
        const int d0 = dt * 32, kc0 = kt * 32;
#pragma unroll
        for (int i = 0; i < 4; i++)
            tile[ty + i * 8][tx] = src[(size_t)(d0 + ty + i * 8) * KDIM + kc0 + tx];
        __syncthreads();
#pragma unroll
        for (int i = 0; i < 4; i++) {
            const int j = slice * 64 + kc0 + ty + i * 8;
            const float v = tile[tx][ty + i * 8];
            // V-region weights feed a 1xTF32 path: pre-round (same value the
            // mainloop would produce by rounding at load). Q,K stay raw.
            g_wt[(size_t)j * EMBED + d0 + tx] = (which == 2) ? tf32r(v) : v;
        }
    } else {
        const int b2 = bid - 3072;           // 0..1023
        const int kt = b2 >> 5, jt = b2 & 31;
        const int k0 = kt * 32, j0 = jt * 32;
#pragma unroll
        for (int i = 0; i < 4; i++)
            tile[ty + i * 8][tx] = w[(size_t)(k0 + ty + i * 8) * EMBED + j0 + tx];
        __syncthreads();
#pragma unroll
        for (int i = 0; i < 4; i++)
            g_wt2[(size_t)(j0 + ty + i * 8) * EMBED + k0 + tx] = tf32r(tile[tx][ty + i * 8]);
    }
}

// ---------------------------------------------------------------------------
// Warp-mma tf32 GEMM (R14-validated):  C[128, 128] = A[128, 1024] @ B^T.
// cp.async double-buffered RAW fp32 staging; tf32 hi/lo split at fragment
// load (lo unrounded: mma truncates, affects 2^-21 terms only).
//   QKV3 : A cvt+split, B cvt+split (raw planes, as R14).
//   QKV1 : A cvt; B pre-rounded at prep (no cvt).
//   OPROJ: A pre-rounded by flash (no cvt); B pre-rounded at prep (no cvt).
// Epilogues: QKV3 -> Q scale+split / K split planes; QKV1 -> direct V^T
// (tf32r) into g_vt; OPROJ -> plain.
// ---------------------------------------------------------------------------
#define MODE_QKV   0
#define MODE_OPROJ 3

#define PA 36              /* smem pitch (floats): conflict-free fragment LDS   */
#define GSTG (2 * 128 * PA)   /* floats per stage: A raw + B raw = 9216 (36 KB) */
#define GEMM_SMEM (2 * GSTG * 4 > 128 * 132 * 4 ? 2 * GSTG * 4 : 128 * 132 * 4) /* 73728 */

template <int MODE, int SPLIT>
__global__ void __launch_bounds__(256, 2) gemm_kernel(
    const float* __restrict__ x, float* __restrict__ outp, int bx0)
{
    extern __shared__ float sf[];
    constexpr int NCH  = 32;          /* K = 1024, chunk 32 */
    constexpr int PEPI = 132;
    constexpr bool ACVT = (MODE == MODE_QKV);               /* OPROJ A pre-rounded */
    constexpr bool BCVT = (MODE == MODE_QKV && SPLIT == 3); /* only raw Q,K weights */

    const int tid  = threadIdx.x;
    const int wid  = tid >> 5;
    const int lane = tid & 31;
    const int g    = lane >> 2;
    const int t    = lane & 3;
    const int wm   = (wid & 3) * 32;
    const int wn   = (wid >> 2) * 64;
    const int bm   = blockIdx.y * 128;

    const float* Abase; const float* Bbase;
    float* Cbase; int ldc;
    int j0 = 0;

    if constexpr (MODE == MODE_QKV) {
        j0 = (blockIdx.x + bx0) * 128;
        Abase = x + (size_t)bm * EMBED;
        Bbase = g_wt + (size_t)j0 * EMBED;
        Cbase = g_qkv + (size_t)bm * QKVW + j0;               ldc = QKVW;
    } else { /* OPROJ */
        Abase = g_heads + (size_t)bm * EMBED;
        Bbase = g_wt2 + (size_t)blockIdx.x * 128 * EMBED;
        Cbase = outp + (size_t)bm * EMBED + blockIdx.x * 128; ldc = EMBED;
    }

    auto fill = [&](int ci, float* stg) {
        const int k0 = ci * 32;
#pragma unroll
        for (int p = 0; p < 4; ++p) {
            const int id = tid + p * 256;
            const int row = id >> 3, ch = (id & 7) * 4;
            cpa16(s2u(stg + row * PA + ch),            Abase + (size_t)row * EMBED + k0 + ch);
            cpa16(s2u(stg + 128 * PA + row * PA + ch), Bbase + (size_t)row * EMBED + k0 + ch);
        }
        asm volatile("cp.async.commit_group;");
    };

    float acc[2][8][4];
#pragma unroll
    for (int mt = 0; mt < 2; mt++)
#pragma unroll
        for (int nt = 0; nt < 8; nt++)
#pragma unroll
            for (int i = 0; i < 4; i++) acc[mt][nt][i] = 0.f;

    fill(0, sf);   // prologue

    for (int ci = 0; ci < NCH; ++ci) {
        float* cur = sf + (ci & 1) * GSTG;
        if (ci + 1 < NCH) {
            fill(ci + 1, sf + ((ci + 1) & 1) * GSTG);
            asm volatile("cp.async.wait_group 1;");
        } else {
            asm volatile("cp.async.wait_group 0;");
        }
        __syncthreads();

        const float* aR = cur;
        const float* bR = cur + 128 * PA;

#pragma unroll
        for (int ks = 0; ks < 4; ++ks) {
            const int kb = ks * 8;
            uint32_t aH[2][4], aL[2][4];
#pragma unroll
            for (int mt = 0; mt < 2; ++mt) {
                const float* ap = aR + (wm + mt * 16 + g) * PA + kb + t;
                const float r0 = ap[0], r1 = ap[8 * PA], r2 = ap[4], r3 = ap[8 * PA + 4];
                float h0, h1, h2, h3;
                if constexpr (ACVT) {
                    h0 = tf32r(r0); h1 = tf32r(r1); h2 = tf32r(r2); h3 = tf32r(r3);
                } else {
                    h0 = r0; h1 = r1; h2 = r2; h3 = r3;
                }
                aH[mt][0] = __float_as_uint(h0);
                aH[mt][1] = __float_as_uint(h1);
                aH[mt][2] = __float_as_uint(h2);
                aH[mt][3] = __float_as_uint(h3);
                if constexpr (SPLIT == 3) {
                    aL[mt][0] = __float_as_uint(r0 - h0);   // lo unrounded (mma truncates)
                    aL[mt][1] = __float_as_uint(r1 - h1);
                    aL[mt][2] = __float_as_uint(r2 - h2);
                    aL[mt][3] = __float_as_uint(r3 - h3);
                }
            }
#pragma unroll
            for (int nt = 0; nt < 8; ++nt) {
                const float* bp = bR + (wn + nt * 8 + g) * PA + kb + t;
                const float rb0 = bp[0], rb1 = bp[4];
                float hb0, hb1;
                if constexpr (BCVT) {
                    hb0 = tf32r(rb0); hb1 = tf32r(rb1);
                } else {
                    hb0 = rb0; hb1 = rb1;
                }
                const uint32_t bH0 = __float_as_uint(hb0);
                const uint32_t bH1 = __float_as_uint(hb1);
#pragma unroll
                for (int mt = 0; mt < 2; ++mt) mma8(acc[mt][nt], aH[mt], bH0, bH1);
                if constexpr (SPLIT == 3) {
                    const uint32_t bL0 = __float_as_uint(rb0 - hb0);
                    const uint32_t bL1 = __float_as_uint(rb1 - hb1);
#pragma unroll
                    for (int mt = 0; mt < 2; ++mt) {
                        mma8(acc[mt][nt], aH[mt], bL0, bL1);
                        mma8(acc[mt][nt], aL[mt], bH0, bH1);
                    }
                }
            }
        }
        __syncthreads();   // all warps done with `cur` before it is refilled
    }

    // ---- epilogue: stage C through smem ----
#pragma unroll
    for (int mt = 0; mt < 2; ++mt)
#pragma unroll
        for (int nt = 0; nt < 8; ++nt) {
            const int row = wm + mt * 16 + g;
            const int col = wn + nt * 8 + t * 2;
            *(float2*)&sf[row * PEPI + col]       = make_float2(acc[mt][nt][0], acc[mt][nt][1]);
            *(float2*)&sf[(row + 8) * PEPI + col] = make_float2(acc[mt][nt][2], acc[mt][nt][3]);
        }
    __syncthreads();

    if constexpr (MODE == MODE_QKV && SPLIT == 1) {
        // V region: transposed tf32r write into g_vt[bh][d][tok].
        // rows r = (tid&7) + 8u: LDS bank = (4*(tid&7) + col) % 32, all 32
        // lanes distinct -> conflict-free; stores land in 32B 8-lane runs.
        const int jv = j0 - 2 * EMBED;
        const int b  = bm >> 11;             // SEQ = 2048
        const int tl = bm & (SEQ - 1);
        const int r0 = tid & 7;
#pragma unroll
        for (int cc = 0; cc < 4; ++cc) {
            const int col = cc * 32 + (tid >> 3);
            const int hh  = (jv + col) >> 6;
            const int dd  = (jv + col) & (KDIM - 1);
            float* dst = g_vt + ((size_t)(b * HEADS + hh) * KDIM + dd) * SEQ + tl;
#pragma unroll
            for (int u = 0; u < 16; ++u) {
                const int r = r0 + u * 8;
                dst[r] = tf32r(sf[r * PEPI + col]);
            }
        }
    } else {
#pragma unroll
        for (int i = tid; i < 128 * 32; i += 256) {
            const int row = i >> 5, c4 = (i & 31) * 4;
            float4 v = *(const float4*)&sf[row * PEPI + c4];
            if constexpr (MODE == MODE_QKV && SPLIT == 3) {
                if (j0 < EMBED) {
                    // Q region: scale by 1/8, split hi/lo (lo unrounded)
                    v.x *= 0.125f; v.y *= 0.125f; v.z *= 0.125f; v.w *= 0.125f;
                    float4 hh, ll;
                    hh.x = tf32r(v.x); ll.x = v.x - hh.x;
                    hh.y = tf32r(v.y); ll.y = v.y - hh.y;
                    hh.z = tf32r(v.z); ll.z = v.z - hh.z;
                    hh.w = tf32r(v.w); ll.w = v.w - hh.w;
                    *(float4*)(Cbase + (size_t)row * ldc + c4) = hh;
                    *(float4*)(g_qlo + (size_t)(bm + row) * EMBED + j0 + c4) = ll;
                } else {
                    // K region: split hi/lo (lo unrounded)
                    float4 hh, ll;
                    hh.x = tf32r(v.x); ll.x = v.x - hh.x;
                    hh.y = tf32r(v.y); ll.y = v.y - hh.y;
                    hh.z = tf32r(v.z); ll.z = v.z - hh.z;
                    hh.w = tf32r(v.w); ll.w = v.w - hh.w;
                    *(float4*)(Cbase + (size_t)row * ldc + c4) = hh;
                    *(float4*)(g_klo + (size_t)(bm + row) * EMBED + (j0 - EMBED) + c4) = ll;
                }
            } else {
                *(float4*)(Cbase + (size_t)row * ldc + c4) = v;
            }
        }
    }
}

// ---------------------------------------------------------------------------
// Flash attention (R14-measured 887us): fused QK^T (3xTF32) + softmax + PV.
// BM=128/CTA, 8 warps x 16 rows; 64-key tiles, double-buffered cp.async.
// Q pre-scaled/pre-split in global -> Q prologue is pure cp.async.
// Output written tf32-rounded so OPROJ can skip its A-side cvt.
// ---------------------------------------------------------------------------
#define FPQ 68             /* pitch mod 32 = 4 -> ALL scalar patterns conflict-free */
#define STG_ROWS 192       /* Kh 64 + Kl 64 + Vt 64 */
#define FLASH_SMEM ((128 * 2 + 2 * STG_ROWS + 128) * FPQ * 4)  /* 208896 B */
#define NKT (SEQ / 64)     /* 32 key tiles */

__global__ void __launch_bounds__(256) flash_kernel()
{
    extern __shared__ float sf[];
    float* Qh  = sf;                       // [row][d]   128 x 64 (hi, scaled)
    float* Ql  = Qh + 128 * FPQ;
    float* St0 = Ql + 128 * FPQ;           // stage 0: Kh|Kl|Vt (64 rows each)
    float* St1 = St0 + STG_ROWS * FPQ;     // stage 1
    float* Ps  = St1 + STG_ROWS * FPQ;     // [row][tok] 128 x 64

    const int tid = threadIdx.x, wid = tid >> 5, lane = tid & 31;
    const int g = lane >> 2, t = lane & 3;
    const int wm = wid * 16;
    const int bm = blockIdx.x * 128;
    const int bh = blockIdx.y, b = bh >> 4, h = bh & (HEADS - 1);

    const float* qhi = g_qkv + (size_t)b * SEQ * QKVW + h * KDIM;
    const float* qlo = g_qlo + (size_t)b * SEQ * EMBED + h * KDIM;
    const float* khi = qhi + EMBED;
    const float* klo = g_klo + (size_t)b * SEQ * EMBED + h * KDIM;
    const float* vtg = g_vt + (size_t)bh * KDIM * SEQ;

    auto fill = [&](int kt0, float* stg) {
        float* Kh = stg;
        float* Kl = stg + 64 * FPQ;
        float* Vt = stg + 128 * FPQ;
#pragma unroll
        for (int p = 0; p < 4; ++p) {
            const int id = tid + p * 256;
            const int row = id >> 4, ch = (id & 15) * 4;
            cpa16(s2u(Kh + row * FPQ + ch), khi + (size_t)(kt0 + row) * QKVW + ch);
            cpa16(s2u(Kl + row * FPQ + ch), klo + (size_t)(kt0 + row) * EMBED + ch);
            cpa16(s2u(Vt + row * FPQ + ch), vtg + (size_t)row * SEQ + kt0 + ch);
        }
        asm volatile("cp.async.commit_group;");
    };

    // Q prologue: pure async copies (group A), then tile-0 fill (group B)
#pragma unroll
    for (int p = 0; p < 8; ++p) {
        const int id = tid + p * 256;
        const int row = id >> 4, ch = (id & 15) * 4;
        cpa16(s2u(Qh + row * FPQ + ch), qhi + (size_t)(bm + row) * QKVW + ch);
        cpa16(s2u(Ql + row * FPQ + ch), qlo + (size_t)(bm + row) * EMBED + ch);
    }
    asm volatile("cp.async.commit_group;");
    fill(0, St0);
    asm volatile("cp.async.wait_group 1;");   // Q copies complete
    __syncthreads();

    // Hoist Q fragments to registers (scalar LDS, conflict-free at pitch 68)
    uint32_t qh[8][4], ql[8][4];
#pragma unroll
    for (int ks = 0; ks < 8; ++ks) {
        const float* ap = Qh + (wm + g) * FPQ + ks * 8 + t;
        const float* al = Ql + (wm + g) * FPQ + ks * 8 + t;
        qh[ks][0] = __float_as_uint(ap[0]);
        qh[ks][1] = __float_as_uint(ap[8 * FPQ]);
        qh[ks][2] = __float_as_uint(ap[4]);
        qh[ks][3] = __float_as_uint(ap[8 * FPQ + 4]);
        ql[ks][0] = __float_as_uint(al[0]);
        ql[ks][1] = __float_as_uint(al[8 * FPQ]);
        ql[ks][2] = __float_as_uint(al[4]);
        ql[ks][3] = __float_as_uint(al[8 * FPQ + 4]);
    }

    float m0 = -1e30f, m1 = -1e30f, l0s = 0.f, l1s = 0.f;
    float o[8][4];
#pragma unroll
    for (int nt = 0; nt < 8; nt++)
#pragma unroll
        for (int i = 0; i < 4; i++) o[nt][i] = 0.f;

    for (int it = 0; it < NKT; ++it) {
        float* cur = (it & 1) ? St1 : St0;
        if (it + 1 < NKT) {
            fill((it + 1) * 64, (it & 1) ? St0 : St1);
            asm volatile("cp.async.wait_group 1;");
        } else {
            asm volatile("cp.async.wait_group 0;");
        }
        __syncthreads();

        float* Kh = cur;
        float* Kl = cur + 64 * FPQ;
        float* Vt = cur + 128 * FPQ;

        // S = Q K^T (3xTF32)
        float s[8][4];
#pragma unroll
        for (int nt = 0; nt < 8; nt++)
#pragma unroll
            for (int i = 0; i < 4; i++) s[nt][i] = 0.f;
#pragma unroll
        for (int ks = 0; ks < 8; ++ks) {
#pragma unroll
            for (int nt = 0; nt < 8; ++nt) {
                const float* bp = Kh + (nt * 8 + g) * FPQ + ks * 8 + t;
                const float* bl = Kl + (nt * 8 + g) * FPQ + ks * 8 + t;
                const uint32_t bH0 = __float_as_uint(bp[0]);
                const uint32_t bH1 = __float_as_uint(bp[4]);
                const uint32_t bL0 = __float_as_uint(bl[0]);
                const uint32_t bL1 = __float_as_uint(bl[4]);
                mma8(s[nt], qh[ks], bH0, bH1);
                mma8(s[nt], qh[ks], bL0, bL1);
                mma8(s[nt], ql[ks], bH0, bH1);
            }
        }

        // Online softmax (rows wm+g and wm+g+8; stats shared within quad)
        float mx0 = -1e30f, mx1 = -1e30f;
#pragma unroll
        for (int nt = 0; nt < 8; nt++) {
            mx0 = fmaxf(mx0, fmaxf(s[nt][0], s[nt][1]));
            mx1 = fmaxf(mx1, fmaxf(s[nt][2], s[nt][3]));
        }
        mx0 = fmaxf(mx0, __shfl_xor_sync(~0u, mx0, 1));
        mx0 = fmaxf(mx0, __shfl_xor_sync(~0u, mx0, 2));
        mx1 = fmaxf(mx1, __shfl_xor_sync(~0u, mx1, 1));
        mx1 = fmaxf(mx1, __shfl_xor_sync(~0u, mx1, 2));
        const float mn0 = fmaxf(m0, mx0), mn1 = fmaxf(m1, mx1);
        const float cr0 = __expf(m0 - mn0), cr1 = __expf(m1 - mn1);
        m0 = mn0; m1 = mn1;
        float ls0 = 0.f, ls1 = 0.f;
#pragma unroll
        for (int nt = 0; nt < 8; nt++) {
            s[nt][0] = __expf(s[nt][0] - mn0);
            s[nt][1] = __expf(s[nt][1] - mn0);
            s[nt][2] = __expf(s[nt][2] - mn1);
            s[nt][3] = __expf(s[nt][3] - mn1);
            ls0 += s[nt][0] + s[nt][1];
            ls1 += s[nt][2] + s[nt][3];
        }
        ls0 += __shfl_xor_sync(~0u, ls0, 1);
        ls0 += __shfl_xor_sync(~0u, ls0, 2);
        ls1 += __shfl_xor_sync(~0u, ls1, 1);
        ls1 += __shfl_xor_sync(~0u, ls1, 2);
        l0s = l0s * cr0 + ls0;
        l1s = l1s * cr1 + ls1;
#pragma unroll
        for (int nt = 0; nt < 8; nt++) {
            o[nt][0] *= cr0; o[nt][1] *= cr0;
            o[nt][2] *= cr1; o[nt][3] *= cr1;
        }

        // Stage P (C-frag layout -> A-frag layout), warp-private rows
#pragma unroll
        for (int nt = 0; nt < 8; nt++) {
            *(float2*)&Ps[(wm + g) * FPQ + nt * 8 + 2 * t] =
                make_float2(tf32r(s[nt][0]), tf32r(s[nt][1]));
            *(float2*)&Ps[(wm + g + 8) * FPQ + nt * 8 + 2 * t] =
                make_float2(tf32r(s[nt][2]), tf32r(s[nt][3]));
        }
        __syncwarp();

        // O += P V (1xTF32)
#pragma unroll
        for (int ks = 0; ks < 8; ++ks) {
            uint32_t a[4];
            const float* ap = Ps + (wm + g) * FPQ + ks * 8 + t;
            a[0] = __float_as_uint(ap[0]);
            a[1] = __float_as_uint(ap[8 * FPQ]);
            a[2] = __float_as_uint(ap[4]);
            a[3] = __float_as_uint(ap[8 * FPQ + 4]);
#pragma unroll
            for (int nt = 0; nt < 8; ++nt) {
                const float* bp = Vt + (nt * 8 + g) * FPQ + ks * 8 + t;
                mma8(o[nt], a, __float_as_uint(bp[0]), __float_as_uint(bp[4]));
            }
        }
        __syncthreads();
    }

    // Epilogue: normalize, pre-round for OPROJ, write heads
    const float i0 = 1.f / l0s, i1 = 1.f / l1s;
    float* dst0 = g_heads + (size_t)(b * SEQ + bm + wm + g) * EMBED + h * KDIM;
    float* dst1 = dst0 + 8 * EMBED;
#pragma unroll
    for (int nt = 0; nt < 8; nt++) {
        *(float2*)(dst0 + nt * 8 + 2 * t) =
            make_float2(tf32r(o[nt][0] * i0), tf32r(o[nt][1] * i0));
        *(float2*)(dst1 + nt * 8 + 2 * t) =
            make_float2(tf32r(o[nt][2] * i1), tf32r(o[nt][3] * i1));
    }
}

// ---------------------------------------------------------------------------
extern "C" void kernel_launch(void* const* d_in, const int* in_sizes, int n_in,
                              void* d_out, int out_size)
{
    const float* x  = (const float*)d_in[0];
    const float* wq = (const float*)d_in[1];
    const float* wk = (const float*)d_in[2];
    const float* wv = (const float*)d_in[3];
    const float* w  = (const float*)d_in[4];
    float* out = (float*)d_out;

    cudaFuncSetAttribute(gemm_kernel<MODE_QKV,   3>,
                         cudaFuncAttributeMaxDynamicSharedMemorySize, GEMM_SMEM);
    cudaFuncSetAttribute(gemm_kernel<MODE_QKV,   1>,
                         cudaFuncAttributeMaxDynamicSharedMemorySize, GEMM_SMEM);
    cudaFuncSetAttribute(gemm_kernel<MODE_OPROJ, 1>,
                         cudaFuncAttributeMaxDynamicSharedMemorySize, GEMM_SMEM);
    cudaFuncSetAttribute(flash_kernel,
                         cudaFuncAttributeMaxDynamicSharedMemorySize, FLASH_SMEM);

    // 0. transpose weights once (V region + w^T pre-rounded, traffic-neutral)
    prep_kernel<<<4096, 256>>>(wq, wk, wv, w);

    // 1a. Q,K projection (3xTF32): cols [0,2048);
    //     epilogue scales/splits Q (g_qlo) and splits K (g_klo).
    gemm_kernel<MODE_QKV, 3>
        <<<dim3(16, TOKENS / 128), 256, GEMM_SMEM>>>(x, out, 0);

    // 1b. V projection (1xTF32, B pre-rounded): cols [2048,3072);
    //     epilogue writes g_vt[bh][d][tok] directly (transposed, tf32r).
    gemm_kernel<MODE_QKV, 1>
        <<<dim3(8, TOKENS / 128), 256, GEMM_SMEM>>>(x, out, 16);

    // 2. fused attention: g_heads = softmax(Q K^T / 8) V  (tf32r output)
    flash_kernel<<<dim3(SEQ / 128, BH), 256, FLASH_SMEM>>>();

    // 3. output projection (tf32, both operands pre-rounded): out = heads @ w
    gemm_kernel<MODE_OPROJ, 1>
        <<<dim3(EMBED / 128, TOKENS / 128), 256, GEMM_SMEM>>>(x, out, 0);
}